// round 6
// baseline (speedup 1.0000x reference)
#include <cuda_runtime.h>

#define C_DIM   128
#define EPSF    1e-5f
#define MAXNZ   8      // max nonzeros per prior column (actual: 2)
#define MAXREG  512    // max regularizer entries (actual: 112)
#define TPB     256
#define WPB     (TPB/32)
#define NBLK    444    // 3 CTAs/SM * 148 SMs
#define LOG2E   1.4426950408889634f
#define LN2F    0.6931471805599453f

// ---- raw MUFU intrinsics (guaranteed single-instruction) ----
__device__ __forceinline__ float ex2f(float x) {
    float y; asm("ex2.approx.ftz.f32 %0, %1;" : "=f"(y) : "f"(x)); return y;
}
__device__ __forceinline__ float lg2f(float x) {
    float y; asm("lg2.approx.ftz.f32 %0, %1;" : "=f"(y) : "f"(x)); return y;
}
__device__ __forceinline__ float rcpf(float x) {
    float y; asm("rcp.approx.ftz.f32 %0, %1;" : "=f"(y) : "f"(x)); return y;
}

// softplus2(x) = log2(1 + 2^x) for |x| <= 1.45, via x/2 + 1 + lncosh series.
// Max err < 1.1e-4 at |x|=1.45 edge, <1e-6 for |x|<0.8.  5 FMA, 0 MUFU.
__device__ __forceinline__ float softplus2_poly(float x) {
    float t = x * x;
    float p = fmaf(fmaf(fmaf(-2.0258e-6f, t, 5.5555e-5f), t, -1.73443e-3f), t, 8.66434e-2f);
    return fmaf(t, p, fmaf(0.5f, x, 1.0f));
}

// ---------------- device scratch (no allocations allowed) ----------------
// column-sparse complement of prior_me, PERMUTED layout: [k][(c&3)*32 + (c>>2)]
__device__ int   g_ci[MAXNZ][C_DIM];
__device__ float g_cv[MAXNZ][C_DIM];
__device__ int   g_colmax;
__device__ int   g_nreg;
__device__ float g_scale_reg;         // SYMBIOTIC * ln2 / n_nz
__device__ int   g_reg_cp[MAXREG];    // child | parent<<16
__device__ float g_reg_co[MAXREG];    // val / (B * row_sum)
__device__ float g_partial[4096];
__device__ unsigned int g_ticket;     // last-block reduction ticket (ends at 0)

// ---------------- setup: 2 independent blocks (phase A | phase B) --------
__global__ void __launch_bounds__(1024)
setup_kernel(const float* __restrict__ prior_me,
             const float* __restrict__ prior_ms, int B) {
    const int t = threadIdx.x;

    if (blockIdx.x == 0) {
        // ---- phase A: columns of comp = 1 - prior_me
        __shared__ int s_ccnt[C_DIM];
        __shared__ int s_cmax;
        if (t < C_DIM) {
            s_ccnt[t] = 0;
            #pragma unroll
            for (int k = 0; k < MAXNZ; ++k) { g_ci[k][t] = 0; g_cv[k][t] = 0.f; }
        }
        if (t == 0) s_cmax = 0;
        __syncthreads();
        const int col  = t & 127;
        const int rseg = t >> 7;               // 0..7, 16 rows each
        const int pc   = (col & 3) * 32 + (col >> 2);
        float v[16];
        #pragma unroll
        for (int i = 0; i < 16; ++i)
            v[i] = 1.0f - prior_me[(rseg * 16 + i) * C_DIM + col];
        #pragma unroll
        for (int i = 0; i < 16; ++i) {
            if (v[i] != 0.0f) {
                int slot = atomicAdd(&s_ccnt[col], 1);
                if (slot < MAXNZ) {
                    g_ci[slot][pc] = rseg * 16 + i;
                    g_cv[slot][pc] = v[i];
                }
            }
        }
        __syncthreads();
        if (t < C_DIM) atomicMax(&s_cmax, s_ccnt[t]);
        __syncthreads();
        if (t == 0) g_colmax = s_cmax;
    } else {
        // ---- phase B: rows of prior_ms
        __shared__ float s_rs8[C_DIM][8];
        __shared__ int   s_nreg, s_nnz;
        if (t == 0) { s_nreg = 0; s_nnz = 0; }
        __syncthreads();
        const int row = t >> 3;
        const int seg = t & 7;                 // 16 cols each, float4 loads
        const float4* pr = (const float4*)(prior_ms + (size_t)row * C_DIM + seg * 16);
        float4 q[4];
        #pragma unroll
        for (int i = 0; i < 4; ++i) q[i] = pr[i];
        float rs = 0.f;
        #pragma unroll
        for (int i = 0; i < 4; ++i) rs += q[i].x + q[i].y + q[i].z + q[i].w;
        s_rs8[row][seg] = rs;
        __syncthreads();
        if (seg == 0) {
            float tot = 0.f;
            #pragma unroll
            for (int k = 0; k < 8; ++k) tot += s_rs8[row][k];
            s_rs8[row][0] = tot;
            if (tot > 0.f) atomicAdd(&s_nnz, 1);
        }
        __syncthreads();
        const float rstot = s_rs8[row][0];
        if (rstot > 0.f) {
            const float inv = 1.0f / ((float)B * rstot);
            const float* qs = (const float*)q;
            #pragma unroll
            for (int i = 0; i < 16; ++i) {
                float v = qs[i];
                if (v != 0.0f) {
                    int slot = atomicAdd(&s_nreg, 1);
                    if (slot < MAXREG) {
                        g_reg_cp[slot] = (seg * 16 + i) | (row << 16);
                        g_reg_co[slot] = v * inv;
                    }
                }
            }
        }
        __syncthreads();
        if (t == 0) {
            g_nreg      = (s_nreg < MAXREG) ? s_nreg : MAXREG;
            int nnz     = (s_nnz > 0) ? s_nnz : 1;
            g_scale_reg = 4.0f * LN2F / (float)nnz;   // SYMBIOTIC=4, ln2 folded
        }
    }
}

// ---------------- main kernel: warp/row, raw MUFU, poly reg, fused reduce -
__global__ void __launch_bounds__(TPB, 3)
main_kernel(const float* __restrict__ logits,
            const float* __restrict__ target,
            const float* __restrict__ weight,
            const float* __restrict__ v1sg, const float* __restrict__ v2sg,
            const float* __restrict__ v1sm, const float* __restrict__ v2sm,
            float* __restrict__ out, int B) {
    __shared__ float sh_w[C_DIM];              // weight * ln2 / (B*C)
    __shared__ float sh_sig[3][C_DIM];         // shift * log2e
    __shared__ float sh_sm[3][C_DIM];          // shift * log2e
    __shared__ float sh_ev[WPB][C_DIM];
    __shared__ float sh_a[WPB][C_DIM];         // clamped activation * log2e
    __shared__ int   s_ci[MAXNZ][C_DIM];       // permuted [k][j*32+l]
    __shared__ float s_cv[MAXNZ][C_DIM];
    __shared__ int   s_rcp[MAXREG];
    __shared__ float s_rco[MAXREG];
    __shared__ float sh_red[TPB];

    const int tid = threadIdx.x;
    const float invBC = LN2F / ((float)B * (float)C_DIM);
    if (tid < C_DIM) {
        sh_w[tid] = weight[tid] * invBC;
        float a1 = v1sg[tid], a2 = v2sg[tid];
        sh_sig[0][tid] = 0.f;
        sh_sig[1][tid] = a1 * LOG2E;
        sh_sig[2][tid] = (a1 - a2) * LOG2E;
        float m1 = v1sm[tid], m2 = v2sm[tid];
        sh_sm[0][tid] = 0.f;
        sh_sm[1][tid] = m1 * LOG2E;
        sh_sm[2][tid] = (m1 - m2) * LOG2E;
        #pragma unroll
        for (int k = 0; k < MAXNZ; ++k) {
            s_ci[k][tid] = g_ci[k][tid];
            s_cv[k][tid] = g_cv[k][tid];
        }
    }
    const int   nreg   = g_nreg;
    const int   colmax = g_colmax;
    const float sreg   = g_scale_reg;
    for (int k = tid; k < nreg; k += TPB) {
        s_rcp[k] = g_reg_cp[k];
        s_rco[k] = g_reg_co[k];
    }
    __syncthreads();

    const int lane   = tid & 31;
    const int w      = tid >> 5;
    const int gwarp  = blockIdx.x * WPB + w;
    const int nwarps = gridDim.x * WPB;

    const float LOGEPS2 = -16.609640474f;      // log2(1e-5)
    const float LOG1ME2 = -1.4427023e-5f;      // log2(1 - 1e-5)
    const float AEPS    = EPSF * LOG2E;        // clamp bounds pre-scaled
    const float A1ME    = (1.f - EPSF) * LOG2E;

    float acc_bce = 0.f, acc_reg = 0.f;

    const float4 w4 = ((const float4*)sh_w)[lane];
    float wj[4] = {w4.x, w4.y, w4.z, w4.w};

    for (int b = gwarp; b < B; b += nwarps) {
        // -------- batch ALL row loads first: MLP = 13 --------
        const float4 tv = __ldg((const float4*)(target + (size_t)b * C_DIM) + lane);
        float4 xs[6], xm[6];
        #pragma unroll
        for (int e = 0; e < 6; ++e)
            xs[e] = __ldg((const float4*)(logits + ((size_t)e * B + b) * C_DIM) + lane);
        #pragma unroll
        for (int e = 0; e < 6; ++e)
            xm[e] = __ldg((const float4*)(logits + ((size_t)(6 + e) * B + b) * C_DIM) + lane);
        float tj[4] = {tv.x, tv.y, tv.z, tv.w};

        // ---------- sigmoid experts 0..5 ----------
        #pragma unroll
        for (int e = 0; e < 6; ++e) {
            const int si = (e >= 3) ? (e - 3) : e;
            const float4 sv = ((const float4*)sh_sig[si])[lane];
            float xj[4] = {xs[e].x, xs[e].y, xs[e].z, xs[e].w};
            float sj[4] = {sv.x, sv.y, sv.z, sv.w};
            float areg[4];
            #pragma unroll
            for (int i = 0; i < 4; ++i) {
                float znl = fmaf(xj[i], -LOG2E, sj[i]);     // -z*log2e
                float ex  = ex2f(znl);                      // e^{-z}
                float sp2 = lg2f(1.f + ex);                 // softplus(-z)/ln2
                float la  = fminf(fmaxf(-sp2,       LOGEPS2), LOG1ME2);
                float l1a = fminf(fmaxf(znl - sp2,  LOGEPS2), LOG1ME2);
                acc_bce -= wj[i] * fmaf(tj[i], la - l1a, l1a);
                if (e >= 3) {
                    float a = rcpf(1.f + ex) * LOG2E;       // sigmoid(z)*log2e
                    areg[i] = fminf(fmaxf(a, AEPS), A1ME);
                }
            }
            if (e >= 3) {
                __syncwarp();
                ((float4*)sh_a[w])[lane] = make_float4(areg[0], areg[1], areg[2], areg[3]);
                __syncwarp();
                for (int k = lane; k < nreg; k += 32) {
                    int cp = s_rcp[k];
                    float x = sh_a[w][cp & 0xffff] - sh_a[w][cp >> 16];  // pre-scaled
                    acc_reg = fmaf(s_rco[k], softplus2_poly(x), acc_reg);
                }
            }
        }

        // ---------- local-softmax experts 6..11 ----------
        #pragma unroll
        for (int j = 0; j < 6; ++j) {
            const int si = (j >= 3) ? (j - 3) : j;
            const float4 sv = ((const float4*)sh_sm[si])[lane];
            float y2[4], ev[4];
            float s = 0.f;
            float xj[4] = {xm[j].x, xm[j].y, xm[j].z, xm[j].w};
            float sj[4] = {sv.x, sv.y, sv.z, sv.w};
            #pragma unroll
            for (int i = 0; i < 4; ++i) {
                y2[i] = fmaf(xj[i], LOG2E, sj[i]);          // (x+shift)*log2e
                ev[i] = ex2f(y2[i]);                        // e^{x+shift}
                s += ev[i];
            }
            #pragma unroll
            for (int o = 16; o > 0; o >>= 1) s += __shfl_xor_sync(0xffffffffu, s, o);
            __syncwarp();
            ((float4*)sh_ev[w])[lane] = make_float4(ev[0], ev[1], ev[2], ev[3]);
            __syncwarp();
            float areg[4];
            #pragma unroll
            for (int i = 0; i < 4; ++i) {
                const int c = 4 * lane + i;
                float corr = 0.f;
                for (int k = 0; k < colmax; ++k) {
                    int   idx = s_ci[k][i * 32 + lane];     // conflict-free
                    float v   = s_cv[k][i * 32 + lane];
                    float e2  = (idx == c) ? ev[i] : sh_ev[w][idx];
                    corr = fmaf(v, e2, corr);
                }
                float dm = s - corr + EPSF;                 // (1-a) numerator
                float dt = dm + ev[i];                      // total denom
                float L2 = lg2f(dt);
                float la  = fminf(fmaxf(y2[i] - L2,       LOGEPS2), LOG1ME2);
                float l1a = fminf(fmaxf(lg2f(dm) - L2,    LOGEPS2), LOG1ME2);
                acc_bce -= wj[i] * fmaf(tj[i], la - l1a, l1a);
                if (j >= 3) {
                    float a = ev[i] * rcpf(dt) * LOG2E;
                    areg[i] = fminf(fmaxf(a, AEPS), A1ME);
                }
            }
            if (j >= 3) {
                __syncwarp();
                ((float4*)sh_a[w])[lane] = make_float4(areg[0], areg[1], areg[2], areg[3]);
                __syncwarp();
                for (int k = lane; k < nreg; k += 32) {
                    int cp = s_rcp[k];
                    float x = sh_a[w][cp & 0xffff] - sh_a[w][cp >> 16];
                    acc_reg = fmaf(s_rco[k], softplus2_poly(x), acc_reg);
                }
            }
        }
    }

    sh_red[tid] = acc_bce + acc_reg * sreg;
    __syncthreads();
    for (int st = TPB / 2; st > 0; st >>= 1) {
        if (tid < st) sh_red[tid] += sh_red[tid + st];
        __syncthreads();
    }
    if (tid == 0) g_partial[blockIdx.x] = sh_red[0];

    // -------- fused final reduction: last block sums in fixed order --------
    __shared__ bool s_last;
    __threadfence();
    if (tid == 0) {
        unsigned int t = atomicAdd(&g_ticket, 1u);
        s_last = (t == (unsigned int)(gridDim.x - 1));
    }
    __syncthreads();
    if (s_last) {
        __threadfence();
        __shared__ double sred[TPB];
        double sd = 0.0;
        for (int i = tid; i < gridDim.x; i += TPB) sd += (double)g_partial[i];
        sred[tid] = sd;
        __syncthreads();
        for (int st = TPB / 2; st > 0; st >>= 1) {
            if (tid < st) sred[tid] += sred[tid + st];
            __syncthreads();
        }
        if (tid == 0) {
            out[0] = (float)sred[0];
            g_ticket = 0;          // reset for next graph replay (deterministic)
        }
    }
}

// ---------------- launch ----------------------
extern "C" void kernel_launch(void* const* d_in, const int* in_sizes, int n_in,
                              void* d_out, int out_size) {
    const float* logits   = (const float*)d_in[0];
    const float* target   = (const float*)d_in[1];
    const float* weight   = (const float*)d_in[2];
    const float* prior_me = (const float*)d_in[3];
    const float* prior_ms = (const float*)d_in[4];
    const float* v1sg     = (const float*)d_in[5];
    const float* v2sg     = (const float*)d_in[6];
    const float* v1sm     = (const float*)d_in[7];
    const float* v2sm     = (const float*)d_in[8];

    const int B = in_sizes[1] / C_DIM;   // target is [B, C]

    setup_kernel<<<2, 1024>>>(prior_me, prior_ms, B);
    main_kernel<<<NBLK, TPB>>>(logits, target, weight, v1sg, v2sg, v1sm, v2sm,
                               (float*)d_out, B);
}

// round 10
// speedup vs baseline: 1.1986x; 1.1986x over previous
#include <cuda_runtime.h>

#define C_DIM   128
#define EPSF    1e-5f
#define MAXNZ   8      // max nonzeros per prior column (actual: 2)
#define MAXREG  512    // max regularizer entries (actual: 112)
#define TPB     256
#define WPB     (TPB/32)
#define NBLK    444    // 3 CTAs/SM * 148 SMs
#define LOG2E   1.4426950408889634f
#define LN2F    0.6931471805599453f

// ---- raw MUFU intrinsics (guaranteed single-instruction) ----
__device__ __forceinline__ float ex2f(float x) {
    float y; asm("ex2.approx.ftz.f32 %0, %1;" : "=f"(y) : "f"(x)); return y;
}
__device__ __forceinline__ float lg2f(float x) {
    float y; asm("lg2.approx.ftz.f32 %0, %1;" : "=f"(y) : "f"(x)); return y;
}
__device__ __forceinline__ float rcpf(float x) {
    float y; asm("rcp.approx.ftz.f32 %0, %1;" : "=f"(y) : "f"(x)); return y;
}
__device__ __forceinline__ unsigned smem_u32(const void* p) {
    unsigned a;
    asm("{ .reg .u64 t; cvta.to.shared.u64 t, %1; cvt.u32.u64 %0, t; }"
        : "=r"(a) : "l"(p));
    return a;
}
__device__ __forceinline__ float lds_f32(unsigned addr) {
    float v; asm volatile("ld.shared.f32 %0, [%1];" : "=f"(v) : "r"(addr)); return v;
}

// ---------------- device scratch (no allocations allowed) ----------------
// column-sparse complement of prior_me, PERMUTED layout: [k][(c&3)*32 + (c>>2)]
__device__ int   g_ci[MAXNZ][C_DIM];
__device__ float g_cv[MAXNZ][C_DIM];
__device__ int   g_colmax;
__device__ int   g_nreg;
__device__ float g_scale_reg;         // SYMBIOTIC * ln2 / n_nz
__device__ int   g_reg_cp[MAXREG];    // child | parent<<16
__device__ float g_reg_co[MAXREG];    // val / (B * row_sum)
__device__ float g_partial[4096];

// ---------------- setup: 2 independent blocks (phase A | phase B) --------
__global__ void __launch_bounds__(1024)
setup_kernel(const float* __restrict__ prior_me,
             const float* __restrict__ prior_ms, int B) {
    const int t = threadIdx.x;

    if (blockIdx.x == 0) {
        // ---- phase A: columns of comp = 1 - prior_me
        __shared__ int s_ccnt[C_DIM];
        __shared__ int s_cmax;
        if (t < C_DIM) {
            s_ccnt[t] = 0;
            #pragma unroll
            for (int k = 0; k < MAXNZ; ++k) { g_ci[k][t] = 0; g_cv[k][t] = 0.f; }
        }
        if (t == 0) s_cmax = 0;
        __syncthreads();
        const int col  = t & 127;
        const int rseg = t >> 7;               // 0..7, 16 rows each
        const int pc   = (col & 3) * 32 + (col >> 2);
        float v[16];
        #pragma unroll
        for (int i = 0; i < 16; ++i)
            v[i] = 1.0f - prior_me[(rseg * 16 + i) * C_DIM + col];
        #pragma unroll
        for (int i = 0; i < 16; ++i) {
            if (v[i] != 0.0f) {
                int slot = atomicAdd(&s_ccnt[col], 1);
                if (slot < MAXNZ) {
                    g_ci[slot][pc] = rseg * 16 + i;
                    g_cv[slot][pc] = v[i];
                }
            }
        }
        __syncthreads();
        if (t < C_DIM) atomicMax(&s_cmax, s_ccnt[t]);
        __syncthreads();
        if (t == 0) g_colmax = s_cmax;
    } else {
        // ---- phase B: rows of prior_ms
        __shared__ float s_rs8[C_DIM][8];
        __shared__ int   s_nreg, s_nnz;
        if (t == 0) { s_nreg = 0; s_nnz = 0; }
        __syncthreads();
        const int row = t >> 3;
        const int seg = t & 7;                 // 16 cols each, float4 loads
        const float4* pr = (const float4*)(prior_ms + (size_t)row * C_DIM + seg * 16);
        float4 q[4];
        #pragma unroll
        for (int i = 0; i < 4; ++i) q[i] = pr[i];
        float rs = 0.f;
        #pragma unroll
        for (int i = 0; i < 4; ++i) rs += q[i].x + q[i].y + q[i].z + q[i].w;
        s_rs8[row][seg] = rs;
        __syncthreads();
        if (seg == 0) {
            float tot = 0.f;
            #pragma unroll
            for (int k = 0; k < 8; ++k) tot += s_rs8[row][k];
            s_rs8[row][0] = tot;
            if (tot > 0.f) atomicAdd(&s_nnz, 1);
        }
        __syncthreads();
        const float rstot = s_rs8[row][0];
        if (rstot > 0.f) {
            const float inv = 1.0f / ((float)B * rstot);
            const float* qs = (const float*)q;
            #pragma unroll
            for (int i = 0; i < 16; ++i) {
                float v = qs[i];
                if (v != 0.0f) {
                    int slot = atomicAdd(&s_nreg, 1);
                    if (slot < MAXREG) {
                        g_reg_cp[slot] = (seg * 16 + i) | (row << 16);
                        g_reg_co[slot] = v * inv;
                    }
                }
            }
        }
        __syncthreads();
        if (t == 0) {
            g_nreg      = (s_nreg < MAXREG) ? s_nreg : MAXREG;
            int nnz     = (s_nnz > 0) ? s_nnz : 1;
            g_scale_reg = 4.0f * LN2F / (float)nnz;   // SYMBIOTIC=4, ln2 folded
        }
    }
}

// ---------------- main kernel: register-resident metadata, raw MUFU -------
__global__ void __launch_bounds__(TPB, 3)
main_kernel(const float* __restrict__ logits,
            const float* __restrict__ target,
            const float* __restrict__ weight,
            const float* __restrict__ v1sg, const float* __restrict__ v2sg,
            const float* __restrict__ v1sm, const float* __restrict__ v2sm,
            int B) {
    __shared__ float sh_w[C_DIM];              // weight * ln2 / (B*C)
    __shared__ float sh_sig[3][C_DIM];         // shift * log2e
    __shared__ float sh_sm[3][C_DIM];          // shift * log2e
    __shared__ float sh_ev[WPB][C_DIM];
    __shared__ float sh_a[WPB][C_DIM];         // clamped activation * log2e
    __shared__ float sh_red[TPB];

    const int tid = threadIdx.x;
    const float invBC = LN2F / ((float)B * (float)C_DIM);
    if (tid < C_DIM) {
        sh_w[tid] = weight[tid] * invBC;
        float a1 = v1sg[tid], a2 = v2sg[tid];
        sh_sig[0][tid] = 0.f;
        sh_sig[1][tid] = a1 * LOG2E;
        sh_sig[2][tid] = (a1 - a2) * LOG2E;
        float m1 = v1sm[tid], m2 = v2sm[tid];
        sh_sm[0][tid] = 0.f;
        sh_sm[1][tid] = m1 * LOG2E;
        sh_sm[2][tid] = (m1 - m2) * LOG2E;
    }
    const int   nreg   = g_nreg;
    const int   colmax = g_colmax;
    const float sreg   = g_scale_reg;
    __syncthreads();

    const int lane   = tid & 31;
    const int w      = tid >> 5;
    const int gwarp  = blockIdx.x * WPB + w;
    const int nwarps = gridDim.x * WPB;

    // ----- hoist ALL loop-invariant metadata into registers -----
    const unsigned a_base = smem_u32(&sh_a[w][0]);
    const unsigned e_base = smem_u32(&sh_ev[w][0]);

    unsigned ga0[4], ga1[4]; float gv0[4], gv1[4];   // denom gather (k=0,1)
    #pragma unroll
    for (int i = 0; i < 4; ++i) {
        int pos = i * 32 + lane;
        ga0[i] = e_base + 4u * (unsigned)g_ci[0][pos];
        gv0[i] = g_cv[0][pos];
        ga1[i] = e_base + 4u * (unsigned)g_ci[1][pos];
        gv1[i] = g_cv[1][pos];
    }
    unsigned rch[4], rp[4]; float rco[4];            // reg entries (<=4/lane)
    #pragma unroll
    for (int kk = 0; kk < 4; ++kk) {
        int k = lane + 32 * kk;
        if (k < nreg) {
            int cp = g_reg_cp[k];
            rch[kk] = a_base + 4u * (unsigned)(cp & 0xffff);
            rp[kk]  = a_base + 4u * (unsigned)(cp >> 16);
            rco[kk] = g_reg_co[k];
        } else {
            rch[kk] = a_base; rp[kk] = a_base; rco[kk] = 0.f;
        }
    }

    const float LOGEPS2 = -16.609640474f;      // log2(1e-5)
    const float LOG1ME2 = -1.4427023e-5f;      // log2(1 - 1e-5)
    const float AEPS    = EPSF * LOG2E;        // clamp bounds pre-scaled
    const float A1ME    = (1.f - EPSF) * LOG2E;

    float acc_bce = 0.f, acc_reg = 0.f;

    const float4 w4 = ((const float4*)sh_w)[lane];
    float wj[4] = {w4.x, w4.y, w4.z, w4.w};

    for (int b = gwarp; b < B; b += nwarps) {
        // -------- batch A: target + 6 sigmoid rows (MLP = 7) --------
        const float4 tv = __ldg((const float4*)(target + (size_t)b * C_DIM) + lane);
        float4 xs[6];
        #pragma unroll
        for (int e = 0; e < 6; ++e)
            xs[e] = __ldg((const float4*)(logits + ((size_t)e * B + b) * C_DIM) + lane);
        float tj[4] = {tv.x, tv.y, tv.z, tv.w};

        // ---------- sigmoid experts 0..2 (no regularizer) ----------
        #pragma unroll
        for (int e = 0; e < 3; ++e) {
            const float4 sv = ((const float4*)sh_sig[e])[lane];
            float xj[4] = {xs[e].x, xs[e].y, xs[e].z, xs[e].w};
            float sj[4] = {sv.x, sv.y, sv.z, sv.w};
            #pragma unroll
            for (int i = 0; i < 4; ++i) {
                float znl = fmaf(xj[i], -LOG2E, sj[i]);     // -z*log2e
                float ex  = ex2f(znl);                      // e^{-z}
                float sp2 = lg2f(1.f + ex);                 // softplus(-z)/ln2
                float la  = fminf(fmaxf(-sp2,       LOGEPS2), LOG1ME2);
                float l1a = fminf(fmaxf(znl - sp2,  LOGEPS2), LOG1ME2);
                acc_bce -= wj[i] * fmaf(tj[i], la - l1a, l1a);
            }
        }

        // -------- batch B: 6 softmax rows (latency covered by e3..5) -----
        float4 xm[6];
        #pragma unroll
        for (int e = 0; e < 6; ++e)
            xm[e] = __ldg((const float4*)(logits + ((size_t)(6 + e) * B + b) * C_DIM) + lane);

        // ---------- sigmoid experts 3..5 (with regularizer) ----------
        #pragma unroll
        for (int e = 3; e < 6; ++e) {
            const float4 sv = ((const float4*)sh_sig[e - 3])[lane];
            float xj[4] = {xs[e].x, xs[e].y, xs[e].z, xs[e].w};
            float sj[4] = {sv.x, sv.y, sv.z, sv.w};
            float areg[4];
            #pragma unroll
            for (int i = 0; i < 4; ++i) {
                float znl = fmaf(xj[i], -LOG2E, sj[i]);
                float ex  = ex2f(znl);
                float sp2 = lg2f(1.f + ex);
                float la  = fminf(fmaxf(-sp2,       LOGEPS2), LOG1ME2);
                float l1a = fminf(fmaxf(znl - sp2,  LOGEPS2), LOG1ME2);
                acc_bce -= wj[i] * fmaf(tj[i], la - l1a, l1a);
                float a = rcpf(1.f + ex) * LOG2E;           // sigmoid(z)*log2e
                areg[i] = fminf(fmaxf(a, AEPS), A1ME);
            }
            __syncwarp();
            ((float4*)sh_a[w])[lane] = make_float4(areg[0], areg[1], areg[2], areg[3]);
            __syncwarp();
            #pragma unroll
            for (int kk = 0; kk < 4; ++kk) {
                float d = lds_f32(rch[kk]) - lds_f32(rp[kk]);
                acc_reg = fmaf(rco[kk], lg2f(1.f + ex2f(d)), acc_reg);
            }
            if (nreg > 128) {                               // generic fallback
                for (int k = 128 + lane; k < nreg; k += 32) {
                    int cp = g_reg_cp[k];
                    float d = sh_a[w][cp & 0xffff] - sh_a[w][cp >> 16];
                    acc_reg = fmaf(g_reg_co[k], lg2f(1.f + ex2f(d)), acc_reg);
                }
            }
        }

        // ---------- local-softmax experts 6..11 ----------
        #pragma unroll
        for (int j = 0; j < 6; ++j) {
            const int si = (j >= 3) ? (j - 3) : j;
            const float4 sv = ((const float4*)sh_sm[si])[lane];
            float y2[4], ev[4];
            float s = 0.f;
            float xj[4] = {xm[j].x, xm[j].y, xm[j].z, xm[j].w};
            float sj[4] = {sv.x, sv.y, sv.z, sv.w};
            #pragma unroll
            for (int i = 0; i < 4; ++i) {
                y2[i] = fmaf(xj[i], LOG2E, sj[i]);          // (x+shift)*log2e
                ev[i] = ex2f(y2[i]);                        // e^{x+shift}
                s += ev[i];
            }
            #pragma unroll
            for (int o = 16; o > 0; o >>= 1) s += __shfl_xor_sync(0xffffffffu, s, o);
            __syncwarp();
            ((float4*)sh_ev[w])[lane] = make_float4(ev[0], ev[1], ev[2], ev[3]);
            __syncwarp();
            float areg[4];
            #pragma unroll
            for (int i = 0; i < 4; ++i) {
                float corr =      gv0[i] * lds_f32(ga0[i]);
                corr = fmaf(gv1[i], lds_f32(ga1[i]), corr);
                if (colmax > 2) {                           // generic fallback
                    int pos = i * 32 + lane;
                    for (int k = 2; k < colmax; ++k)
                        corr = fmaf(g_cv[k][pos], sh_ev[w][g_ci[k][pos]], corr);
                }
                float dm = s - corr + EPSF;                 // (1-a) numerator
                float dt = dm + ev[i];                      // total denom
                float L2 = lg2f(dt);
                float la  = fminf(fmaxf(y2[i] - L2,       LOGEPS2), LOG1ME2);
                float l1a = fminf(fmaxf(lg2f(dm) - L2,    LOGEPS2), LOG1ME2);
                acc_bce -= wj[i] * fmaf(tj[i], la - l1a, l1a);
                if (j >= 3) {
                    float a = ev[i] * rcpf(dt) * LOG2E;
                    areg[i] = fminf(fmaxf(a, AEPS), A1ME);
                }
            }
            if (j >= 3) {
                __syncwarp();
                ((float4*)sh_a[w])[lane] = make_float4(areg[0], areg[1], areg[2], areg[3]);
                __syncwarp();
                #pragma unroll
                for (int kk = 0; kk < 4; ++kk) {
                    float d = lds_f32(rch[kk]) - lds_f32(rp[kk]);
                    acc_reg = fmaf(rco[kk], lg2f(1.f + ex2f(d)), acc_reg);
                }
                if (nreg > 128) {
                    for (int k = 128 + lane; k < nreg; k += 32) {
                        int cp = g_reg_cp[k];
                        float d = sh_a[w][cp & 0xffff] - sh_a[w][cp >> 16];
                        acc_reg = fmaf(g_reg_co[k], lg2f(1.f + ex2f(d)), acc_reg);
                    }
                }
            }
        }
    }

    sh_red[tid] = acc_bce + acc_reg * sreg;
    __syncthreads();
    for (int st = TPB / 2; st > 0; st >>= 1) {
        if (tid < st) sh_red[tid] += sh_red[tid + st];
        __syncthreads();
    }
    if (tid == 0) g_partial[blockIdx.x] = sh_red[0];
}

// ---------------- final reduce (fp64 for stability) ----------------------
__global__ void reduce_kernel(float* __restrict__ out, int n) {
    __shared__ double sred[256];
    double s = 0.0;
    for (int i = threadIdx.x; i < n; i += 256) s += (double)g_partial[i];
    sred[threadIdx.x] = s;
    __syncthreads();
    for (int st = 128; st > 0; st >>= 1) {
        if (threadIdx.x < st) sred[threadIdx.x] += sred[threadIdx.x + st];
        __syncthreads();
    }
    if (threadIdx.x == 0) out[0] = (float)sred[0];
}

// ---------------- launch ----------------------
extern "C" void kernel_launch(void* const* d_in, const int* in_sizes, int n_in,
                              void* d_out, int out_size) {
    const float* logits   = (const float*)d_in[0];
    const float* target   = (const float*)d_in[1];
    const float* weight   = (const float*)d_in[2];
    const float* prior_me = (const float*)d_in[3];
    const float* prior_ms = (const float*)d_in[4];
    const float* v1sg     = (const float*)d_in[5];
    const float* v2sg     = (const float*)d_in[6];
    const float* v1sm     = (const float*)d_in[7];
    const float* v2sm     = (const float*)d_in[8];

    const int B = in_sizes[1] / C_DIM;   // target is [B, C]

    setup_kernel<<<2, 1024>>>(prior_me, prior_ms, B);
    main_kernel<<<NBLK, TPB>>>(logits, target, weight, v1sg, v2sg, v1sm, v2sm, B);
    reduce_kernel<<<1, 256>>>((float*)d_out, NBLK);
}